// round 12
// baseline (speedup 1.0000x reference)
#include <cuda_runtime.h>
#include <math.h>

// Problem constants (reference hardcodes H=W=512, N=4096).
#define NG     4096
#define HIMG   512
#define WIMG   512
#define HW     (HIMG * WIMG)
#define TW     16
#define TH     8
#define TXN    (WIMG / TW)     // 32 tiles in x
#define TYN    (HIMG / TH)     // 64 tiles in y
#define NTILES (TXN * TYN)     // 2048
#define CAP    128             // per-tile capacity (observed max ~13-25)
#define NB     1024            // blocks: proven single co-resident wave
#define NT     128             // threads per block
#define NGRP   32              // arrival-tree groups
#define GSZ    (NB / NGRP)     // 32 blocks per group

// Static device scratch (zero-initialized at load; kernel is self-resetting:
// every counter/flag returns to 0 before the owning block finishes, so each
// graph replay sees identical initial state).
__device__ float4 g_la[NTILES * CAP];       // px, py, 0.5*c0, c1
__device__ float4 g_lb[NTILES * CAP];       // 0.5*c2, feat_r, feat_g, feat_b
__device__ float4 g_lc[NTILES * CAP];       // geo_r, geo_g, geo_b, unused
__device__ int    g_tile_cnt[NTILES];
__device__ int    g_grp[NGRP * 32];         // group arrive counters, 128B apart
__device__ int    g_master;                 // master arrive counter
__device__ int    g_flag[NB];               // per-block release flags

__global__ __launch_bounds__(NT, 8)
void fused_kernel(const float* __restrict__ xyz,
                  const float* __restrict__ chol,
                  const float* __restrict__ feat,
                  const float* __restrict__ rcol,
                  float* __restrict__ out) {
    int b    = blockIdx.x;
    int tid  = threadIdx.x;
    int wid  = tid >> 5;
    int lane = tid & 31;

    __shared__ int s_rel;   // 1 if this block is the barrier releaser

    // -------- Phase A: one warp per gaussian; one lane per covered tile ----
    {
        int i = b * 4 + wid;   // exactly NG = NB*4 gaussians

        if (lane == 0) out[7 * HW + i] = 1.0f;  // opac output = ones(N,1)

        // All lanes compute the projection redundantly (broadcast loads).
        float mx = tanhf(xyz[2 * i + 0]);
        float my = tanhf(xyz[2 * i + 1]);

        float l0 = chol[3 * i + 0] + 0.5f;
        float l1 = chol[3 * i + 1];
        float l2 = chol[3 * i + 2] + 0.5f;

        float s00 = l0 * l0;
        float s01 = l0 * l1;
        float s11 = l1 * l1 + l2 * l2;
        float det = s00 * s11 - s01 * s01;
        float inv = 1.0f / det;

        float px = 0.5f * ((mx + 1.0f) * (float)WIMG - 1.0f);
        float py = 0.5f * ((my + 1.0f) * (float)HIMG - 1.0f);

        float4 pa = make_float4(px, py, 0.5f * s11 * inv, -s01 * inv);
        float4 pb = make_float4(0.5f * s00 * inv,
                                feat[3 * i], feat[3 * i + 1], feat[3 * i + 2]);
        float4 pc = make_float4(0.5f * rcol[3 * i], 0.5f * rcol[3 * i + 1],
                                0.5f * rcol[3 * i + 2], 0.0f);

        // Exact extents: live requires sigma <= ln(255) = 5.5413 (+eps).
        const float T = 5.545f;
        float hx = sqrtf(2.0f * T * s00);
        float hy = sqrtf(2.0f * T * s11);

        int x0 = max(0,       (int)ceilf ((px - hx - (float)(TW - 1)) * (1.0f / TW)));
        int x1 = min(TXN - 1, (int)floorf((px + hx) * (1.0f / TW)));
        int y0 = max(0,       (int)ceilf ((py - hy - (float)(TH - 1)) * (1.0f / TH)));
        int y1 = min(TYN - 1, (int)floorf((py + hy) * (1.0f / TH)));

        int nx = x1 - x0 + 1;
        int ny = y1 - y0 + 1;
        int nt = (nx > 0 && ny > 0) ? nx * ny : 0;   // <= ~12 in practice

        for (int s = lane; s < nt; s += 32) {        // one atomic per lane
            int tx = x0 + (s % nx);
            int ty = y0 + (s / nx);
            int t  = ty * TXN + tx;
            int slot = atomicAdd(&g_tile_cnt[t], 1);
            if (slot < CAP) {
                int p = t * CAP + slot;
                g_la[p] = pa;
                g_lb[p] = pb;
                g_lc[p] = pc;
            }
        }
    }

    // -------- Grid barrier: tree arrive, distributed-flag release ----------
    // Max same-address RMW chain is 32 (group) + 32 (master), not 1024.
    __syncthreads();
    if (tid == 0) {
        __threadfence();                        // publish phase-A stores
        int grp = b >> 5;                       // 32 groups of 32 blocks
        int ga  = atomicAdd(&g_grp[grp * 32], 1);
        int rel = 0;
        if (ga == GSZ - 1) {                    // last of this group
            g_grp[grp * 32] = 0;                // self-reset (no one else touches it now)
            int ma = atomicAdd(&g_master, 1);
            if (ma == NGRP - 1) {               // last group overall -> releaser
                g_master = 0;                   // self-reset
                rel = 1;
            }
        }
        s_rel = rel;
    }
    __syncthreads();
    if (s_rel) {
        // Releaser: 128 threads fan the release to per-block flags (8 each),
        // spread across L2 slices.
        #pragma unroll
        for (int k = 0; k < NB / NT; k++) {
            *(volatile int*)&g_flag[k * NT + tid] = 1;
        }
        if (tid == 0) g_flag[b] = 0;            // clear own flag (self-reset)
    } else if (tid == 0) {
        volatile int* f = &g_flag[b];            // poll OWN flag: no hot address
        while (*f == 0) __nanosleep(64);
        *f = 0;                                  // self-reset for next replay
        __threadfence();                         // acquire
    }
    __syncthreads();

    // -------- Phase B: raster 2 tiles (16x8 px), staged together -----------
    __shared__ float4 sa[2][CAP];
    __shared__ float4 sb[2][CAP];
    __shared__ float4 sc[2][CAP];

    int tile0 = b;
    int tile1 = b + NB;

    int cnt0 = min(g_tile_cnt[tile0], CAP);
    int cnt1 = min(g_tile_cnt[tile1], CAP);

    if (tid < cnt0) {
        int p = tile0 * CAP + tid;
        sa[0][tid] = g_la[p];
        sb[0][tid] = g_lb[p];
        sc[0][tid] = g_lc[p];
    }
    if (tid < cnt1) {
        int p = tile1 * CAP + tid;
        sa[1][tid] = g_la[p];
        sb[1][tid] = g_lb[p];
        sc[1][tid] = g_lc[p];
    }
    __syncthreads();

    int lx = tid & (TW - 1);
    int ly = tid >> 4;              // 0..7

    #pragma unroll
    for (int tt = 0; tt < 2; tt++) {
        int tile  = (tt == 0) ? tile0 : tile1;
        int cnt   = (tt == 0) ? cnt0  : cnt1;
        int tilex = tile & (TXN - 1);
        int tiley = tile >> 5;      // tile / TXN

        int   pxi = tilex * TW + lx;
        int   pyi = tiley * TH + ly;
        float pxf = (float)pxi;
        float pyf = (float)pyi;

        float ar = 0.f, ag = 0.f, ab = 0.f;
        float gr = 0.f, gg = 0.f, gb = 0.f;
        float aa = 0.f;

        #pragma unroll 4
        for (int j = 0; j < cnt; j++) {
            float4 a = sa[tt][j];
            float dx = a.x - pxf;
            float dy = a.y - pyf;
            float c2h = sb[tt][j].x;
            float sigma = fmaf(dx, fmaf(a.z, dx, a.w * dy), c2h * dy * dy);
            float e = __expf(-sigma);
            bool live = (sigma >= 0.0f) && (e >= (1.0f / 255.0f));
            float alpha = live ? fminf(0.999f, e) : 0.0f;
            float4 bb = sb[tt][j];
            float4 cc = sc[tt][j];
            ar += alpha * bb.y;
            ag += alpha * bb.z;
            ab += alpha * bb.w;
            gr += alpha * cc.x;
            gg += alpha * cc.y;
            gb += alpha * cc.z;
            aa += alpha;
        }

        int pix = pyi * WIMG + pxi;
        out[0 * HW + pix] = fminf(1.0f, fmaxf(0.0f, ar));
        out[1 * HW + pix] = fminf(1.0f, fmaxf(0.0f, ag));
        out[2 * HW + pix] = fminf(1.0f, fmaxf(0.0f, ab));
        out[3 * HW + pix] = fminf(1.0f, fmaxf(0.0f, gr));
        out[4 * HW + pix] = fminf(1.0f, fmaxf(0.0f, gg));
        out[5 * HW + pix] = fminf(1.0f, fmaxf(0.0f, gb));
        out[6 * HW + pix] = aa;

        if (tid == 0) g_tile_cnt[tile] = 0;   // restore zero state
    }
    // No exit barrier: all shared state is already self-reset. Blocks retire
    // independently (no retirement serialization).
}

extern "C" void kernel_launch(void* const* d_in, const int* in_sizes, int n_in,
                              void* d_out, int out_size) {
    const float* xyz  = (const float*)d_in[0];
    const float* chol = (const float*)d_in[1];
    const float* feat = (const float*)d_in[2];
    const float* rcol = (const float*)d_in[3];
    float* out = (float*)d_out;

    fused_kernel<<<NB, NT>>>(xyz, chol, feat, rcol, out);
}

// round 16
// speedup vs baseline: 1.0912x; 1.0912x over previous
#include <cuda_runtime.h>
#include <math.h>

// Problem constants (reference hardcodes H=W=512, N=4096).
#define NG     4096
#define HIMG   512
#define WIMG   512
#define HW     (HIMG * WIMG)
#define TW     16
#define TH     8
#define TXN    (WIMG / TW)     // 32 tiles in x
#define TYN    (HIMG / TH)     // 64 tiles in y
#define NTILES (TXN * TYN)     // 2048
#define CAP    64              // per-tile capacity (observed max ~25)

// Static device scratch (zero-initialized at load; K2 resets each tile count
// after use so every graph replay sees identical initial state).
__device__ float4 g_la[NTILES * CAP];       // px, py, 0.5*c0, c1
__device__ float4 g_lb[NTILES * CAP];       // 0.5*c2, feat_r, feat_g, feat_b
__device__ float4 g_lc[NTILES * CAP];       // geo_r, geo_g, geo_b, unused
__device__ int    g_tile_cnt[NTILES];

// ---------------- K1: project + bin (one warp per gaussian) ----------------
__global__ __launch_bounds__(256)
void project_bin_kernel(const float* __restrict__ xyz,
                        const float* __restrict__ chol,
                        const float* __restrict__ feat,
                        const float* __restrict__ rcol,
                        float* __restrict__ opac_out) {
    int wid  = (blockIdx.x * blockDim.x + threadIdx.x) >> 5;  // global warp id
    int lane = threadIdx.x & 31;
    int i    = wid;                                           // one gaussian/warp

    if (lane == 0) opac_out[i] = 1.0f;   // opac output = ones(N,1)

    // All lanes compute the projection redundantly (broadcast loads).
    float mx = tanhf(xyz[2 * i + 0]);
    float my = tanhf(xyz[2 * i + 1]);

    float l0 = chol[3 * i + 0] + 0.5f;
    float l1 = chol[3 * i + 1];
    float l2 = chol[3 * i + 2] + 0.5f;

    float s00 = l0 * l0;
    float s01 = l0 * l1;
    float s11 = l1 * l1 + l2 * l2;
    float det = s00 * s11 - s01 * s01;
    float inv = 1.0f / det;

    float px = 0.5f * ((mx + 1.0f) * (float)WIMG - 1.0f);
    float py = 0.5f * ((my + 1.0f) * (float)HIMG - 1.0f);

    float4 pa = make_float4(px, py, 0.5f * s11 * inv, -s01 * inv);
    float4 pb = make_float4(0.5f * s00 * inv,
                            feat[3 * i], feat[3 * i + 1], feat[3 * i + 2]);
    float4 pc = make_float4(0.5f * rcol[3 * i], 0.5f * rcol[3 * i + 1],
                            0.5f * rcol[3 * i + 2], 0.0f);

    // Exact extents: live requires sigma <= ln(255) = 5.5413 (+eps).
    const float T = 5.545f;
    float hx = sqrtf(2.0f * T * s00);
    float hy = sqrtf(2.0f * T * s11);

    int x0 = max(0,       (int)ceilf ((px - hx - (float)(TW - 1)) * (1.0f / TW)));
    int x1 = min(TXN - 1, (int)floorf((px + hx) * (1.0f / TW)));
    int y0 = max(0,       (int)ceilf ((py - hy - (float)(TH - 1)) * (1.0f / TH)));
    int y1 = min(TYN - 1, (int)floorf((py + hy) * (1.0f / TH)));

    int nx = x1 - x0 + 1;
    int ny = y1 - y0 + 1;
    int nt = (nx > 0 && ny > 0) ? nx * ny : 0;   // <= ~12 in practice

    for (int s = lane; s < nt; s += 32) {        // one atomic per lane
        int tx = x0 + (s % nx);
        int ty = y0 + (s / nx);
        int t  = ty * TXN + tx;
        int slot = atomicAdd(&g_tile_cnt[t], 1);
        if (slot < CAP) {
            int p = t * CAP + slot;
            g_la[p] = pa;
            g_lb[p] = pb;
            g_lc[p] = pc;
        }
    }
}

// ---------------- K2: raster one 16x8 tile per block ------------------------
__global__ __launch_bounds__(128)
void raster_kernel(float* __restrict__ out) {
    __shared__ float4 sa[CAP];
    __shared__ float4 sb[CAP];
    __shared__ float4 sc[CAP];

    int tile = blockIdx.x;
    int tid  = threadIdx.x;

    int cnt = min(g_tile_cnt[tile], CAP);

    if (tid < cnt) {
        int p = tile * CAP + tid;
        sa[tid] = g_la[p];
        sb[tid] = g_lb[p];
        sc[tid] = g_lc[p];
    }
    __syncthreads();

    int tilex = tile & (TXN - 1);
    int tiley = tile >> 5;          // tile / TXN
    int lx = tid & (TW - 1);
    int ly = tid >> 4;              // 0..7

    int   pxi = tilex * TW + lx;
    int   pyi = tiley * TH + ly;
    float pxf = (float)pxi;
    float pyf = (float)pyi;

    float ar = 0.f, ag = 0.f, ab = 0.f;
    float gr = 0.f, gg = 0.f, gb = 0.f;
    float aa = 0.f;

    #pragma unroll 4
    for (int j = 0; j < cnt; j++) {
        float4 a = sa[j];
        float dx = a.x - pxf;
        float dy = a.y - pyf;
        float c2h = sb[j].x;
        float sigma = fmaf(dx, fmaf(a.z, dx, a.w * dy), c2h * dy * dy);
        float e = __expf(-sigma);
        bool live = (sigma >= 0.0f) && (e >= (1.0f / 255.0f));
        float alpha = live ? fminf(0.999f, e) : 0.0f;
        float4 bb = sb[j];
        float4 cc = sc[j];
        ar += alpha * bb.y;
        ag += alpha * bb.z;
        ab += alpha * bb.w;
        gr += alpha * cc.x;
        gg += alpha * cc.y;
        gb += alpha * cc.z;
        aa += alpha;
    }

    int pix = pyi * WIMG + pxi;
    // render (clipped), channel-major [3, H, W]
    out[0 * HW + pix] = fminf(1.0f, fmaxf(0.0f, ar));
    out[1 * HW + pix] = fminf(1.0f, fmaxf(0.0f, ag));
    out[2 * HW + pix] = fminf(1.0f, fmaxf(0.0f, ab));
    // gauss_render (clipped)
    out[3 * HW + pix] = fminf(1.0f, fmaxf(0.0f, gr));
    out[4 * HW + pix] = fminf(1.0f, fmaxf(0.0f, gg));
    out[5 * HW + pix] = fminf(1.0f, fmaxf(0.0f, gb));
    // alpha map (unclipped)
    out[6 * HW + pix] = aa;

    // Restore zero state for the next graph replay.
    if (tid == 0) g_tile_cnt[tile] = 0;
}

extern "C" void kernel_launch(void* const* d_in, const int* in_sizes, int n_in,
                              void* d_out, int out_size) {
    const float* xyz  = (const float*)d_in[0];
    const float* chol = (const float*)d_in[1];
    const float* feat = (const float*)d_in[2];
    const float* rcol = (const float*)d_in[3];

    float* out  = (float*)d_out;
    float* opac = out + 7 * HW;  // render(3HW) + gauss(3HW) + alpha(HW), then opac(NG)

    // 4096 warps, one per gaussian: 512 blocks x 256 threads.
    project_bin_kernel<<<NG / 8, 256>>>(xyz, chol, feat, rcol, opac);
    raster_kernel<<<NTILES, 128>>>(out);
}

// round 17
// speedup vs baseline: 1.1866x; 1.0875x over previous
#include <cuda_runtime.h>
#include <math.h>

// Problem constants (reference hardcodes H=W=512, N=4096).
#define NG     4096
#define HIMG   512
#define WIMG   512
#define HW     (HIMG * WIMG)
#define TW     16
#define TH     8
#define TXN    (WIMG / TW)     // 32 tiles in x
#define TYN    (HIMG / TH)     // 64 tiles in y
#define NTILES (TXN * TYN)     // 2048
#define CAP    64              // per-tile capacity (observed max ~25)

// Static device scratch (zero-initialized at load; K2 resets each tile count
// after use so every graph replay sees identical initial state).
__device__ float4 g_la[NTILES * CAP];       // px, py, 0.5*c0, c1
__device__ float4 g_lb[NTILES * CAP];       // 0.5*c2, feat_r, feat_g, feat_b
__device__ float4 g_lc[NTILES * CAP];       // geo_r, geo_g, geo_b, unused
__device__ int    g_tile_cnt[NTILES];

// ---------------- K1: project + bin (one warp per gaussian) ----------------
__global__ __launch_bounds__(256)
void project_bin_kernel(const float* __restrict__ xyz,
                        const float* __restrict__ chol,
                        const float* __restrict__ feat,
                        const float* __restrict__ rcol,
                        float* __restrict__ opac_out) {
    int wid  = (blockIdx.x * blockDim.x + threadIdx.x) >> 5;  // global warp id
    int lane = threadIdx.x & 31;
    int i    = wid;                                           // one gaussian/warp

    if (lane == 0) opac_out[i] = 1.0f;   // opac output = ones(N,1)

    // All lanes compute the projection redundantly (broadcast loads).
    float mx = tanhf(xyz[2 * i + 0]);
    float my = tanhf(xyz[2 * i + 1]);

    float l0 = chol[3 * i + 0] + 0.5f;
    float l1 = chol[3 * i + 1];
    float l2 = chol[3 * i + 2] + 0.5f;

    float s00 = l0 * l0;
    float s01 = l0 * l1;
    float s11 = l1 * l1 + l2 * l2;
    float det = s00 * s11 - s01 * s01;
    float inv = 1.0f / det;

    float px = 0.5f * ((mx + 1.0f) * (float)WIMG - 1.0f);
    float py = 0.5f * ((my + 1.0f) * (float)HIMG - 1.0f);

    float4 pa = make_float4(px, py, 0.5f * s11 * inv, -s01 * inv);
    float4 pb = make_float4(0.5f * s00 * inv,
                            feat[3 * i], feat[3 * i + 1], feat[3 * i + 2]);
    float4 pc = make_float4(0.5f * rcol[3 * i], 0.5f * rcol[3 * i + 1],
                            0.5f * rcol[3 * i + 2], 0.0f);

    // Exact extents: live requires sigma <= ln(255) = 5.5413 (+eps).
    const float T = 5.545f;
    float hx = sqrtf(2.0f * T * s00);
    float hy = sqrtf(2.0f * T * s11);

    int x0 = max(0,       (int)ceilf ((px - hx - (float)(TW - 1)) * (1.0f / TW)));
    int x1 = min(TXN - 1, (int)floorf((px + hx) * (1.0f / TW)));
    int y0 = max(0,       (int)ceilf ((py - hy - (float)(TH - 1)) * (1.0f / TH)));
    int y1 = min(TYN - 1, (int)floorf((py + hy) * (1.0f / TH)));

    int nx = x1 - x0 + 1;
    int ny = y1 - y0 + 1;
    int nt = (nx > 0 && ny > 0) ? nx * ny : 0;   // <= ~12 in practice

    for (int s = lane; s < nt; s += 32) {        // one atomic per lane
        int tx = x0 + (s % nx);
        int ty = y0 + (s / nx);
        int t  = ty * TXN + tx;
        int slot = atomicAdd(&g_tile_cnt[t], 1);
        if (slot < CAP) {
            int p = t * CAP + slot;
            g_la[p] = pa;
            g_lb[p] = pb;
            g_lc[p] = pc;
        }
    }
}

// ---------------- K2: raster one 16x8 tile per block ------------------------
__global__ __launch_bounds__(128)
void raster_kernel(float* __restrict__ out) {
    __shared__ float4 sa[CAP];
    __shared__ float4 sb[CAP];
    __shared__ float4 sc[CAP];

    int tile = blockIdx.x;
    int tid  = threadIdx.x;

    int cnt = min(g_tile_cnt[tile], CAP);

    if (tid < cnt) {
        int p = tile * CAP + tid;
        sa[tid] = g_la[p];
        sb[tid] = g_lb[p];
        sc[tid] = g_lc[p];
    }
    __syncthreads();

    int tilex = tile & (TXN - 1);
    int tiley = tile >> 5;          // tile / TXN
    int lx = tid & (TW - 1);
    int ly = tid >> 4;              // 0..7

    int   pxi = tilex * TW + lx;
    int   pyi = tiley * TH + ly;
    float pxf = (float)pxi;
    float pyf = (float)pyi;

    float ar = 0.f, ag = 0.f, ab = 0.f;
    float gr = 0.f, gg = 0.f, gb = 0.f;
    float aa = 0.f;

    #pragma unroll 4
    for (int j = 0; j < cnt; j++) {
        float4 a = sa[j];
        float dx = a.x - pxf;
        float dy = a.y - pyf;
        float c2h = sb[j].x;
        float sigma = fmaf(dx, fmaf(a.z, dx, a.w * dy), c2h * dy * dy);
        float e = __expf(-sigma);
        bool live = (sigma >= 0.0f) && (e >= (1.0f / 255.0f));
        float alpha = live ? fminf(0.999f, e) : 0.0f;
        float4 bb = sb[j];
        float4 cc = sc[j];
        ar += alpha * bb.y;
        ag += alpha * bb.z;
        ab += alpha * bb.w;
        gr += alpha * cc.x;
        gg += alpha * cc.y;
        gb += alpha * cc.z;
        aa += alpha;
    }

    int pix = pyi * WIMG + pxi;
    // render (clipped), channel-major [3, H, W]
    out[0 * HW + pix] = fminf(1.0f, fmaxf(0.0f, ar));
    out[1 * HW + pix] = fminf(1.0f, fmaxf(0.0f, ag));
    out[2 * HW + pix] = fminf(1.0f, fmaxf(0.0f, ab));
    // gauss_render (clipped)
    out[3 * HW + pix] = fminf(1.0f, fmaxf(0.0f, gr));
    out[4 * HW + pix] = fminf(1.0f, fmaxf(0.0f, gg));
    out[5 * HW + pix] = fminf(1.0f, fmaxf(0.0f, gb));
    // alpha map (unclipped)
    out[6 * HW + pix] = aa;

    // Restore zero state for the next graph replay.
    if (tid == 0) g_tile_cnt[tile] = 0;
}

extern "C" void kernel_launch(void* const* d_in, const int* in_sizes, int n_in,
                              void* d_out, int out_size) {
    const float* xyz  = (const float*)d_in[0];
    const float* chol = (const float*)d_in[1];
    const float* feat = (const float*)d_in[2];
    const float* rcol = (const float*)d_in[3];

    float* out  = (float*)d_out;
    float* opac = out + 7 * HW;  // render(3HW) + gauss(3HW) + alpha(HW), then opac(NG)

    // 4096 warps, one per gaussian: 512 blocks x 256 threads.
    project_bin_kernel<<<NG / 8, 256>>>(xyz, chol, feat, rcol, opac);
    raster_kernel<<<NTILES, 128>>>(out);
}